// round 15
// baseline (speedup 1.0000x reference)
#include <cuda_runtime.h>
#include <cuda_bf16.h>
#include <cstdint>

// out[s,a] = values[index[s,a]]
// index: int32 [33,554,432], values: float [100], out: float [33,554,432]
//
// FINAL (converged, frozen). HBM-bound gather at ~7.4 TB/s goodput
// (~92% of 8 TB/s spec); kernel ~36.2us vs 33.5us absolute traffic floor.
//
// Complete sweep (kernel us):
//   MLP=1 41.4 | MLP=4/256t 37.1-37.4 | MLP=8 37.5 | 512t 38.0
//   persistent 38.2 | replicated-table 39.1 | 64t 36.22
//   128t+smem+stcs 36.19-36.93 (BEST, this config)
//   128t+stwb 36.99 | 128t no-smem __ldg 37.38
// dur_us noise floor ~43.5; kernel run-to-run variance ~±0.4us.
//
// Winning recipe:
//  - 128 threads/block, flat grid 16384 CTAs (smooth L1tex queue pressure,
//    cheap barriers, occ ~85%)
//  - single-copy 512B smem table, one predicated load to fill
//  - MLP = 4 front-batched int4 loads / float4 stores (28 regs)
//  - __ldcs loads + __stcs stores (evict-first on both touch-once streams)

static constexpr int VOCAB_MAX       = 128;
static constexpr int THREADS         = 128;
static constexpr int VEC_PER_THREAD  = 4;                        // 4 x int4 = 16 elems/thread
static constexpr int VEC_PER_BLOCK   = THREADS * VEC_PER_THREAD; // 512 vec4/block

__global__ void __launch_bounds__(THREADS) gather_final128_kernel(
    const int4* __restrict__ idx4,
    const float* __restrict__ values,
    float4* __restrict__ out4,
    int n_vec4,
    int n_values)
{
    __shared__ float s_vals[VOCAB_MAX];
    if (threadIdx.x < n_values) {
        s_vals[threadIdx.x] = values[threadIdx.x];
    }
    __syncthreads();

    int base = blockIdx.x * VEC_PER_BLOCK + threadIdx.x;

    if (base + (VEC_PER_THREAD - 1) * THREADS < n_vec4) {
        // Fast path: every block for this shape (8,388,608 / 512 = 16384).
        int4 v[VEC_PER_THREAD];
        #pragma unroll
        for (int k = 0; k < VEC_PER_THREAD; k++) {
            v[k] = __ldcs(&idx4[base + k * THREADS]);
        }
        #pragma unroll
        for (int k = 0; k < VEC_PER_THREAD; k++) {
            float4 r;
            r.x = s_vals[v[k].x];
            r.y = s_vals[v[k].y];
            r.z = s_vals[v[k].z];
            r.w = s_vals[v[k].w];
            __stcs(&out4[base + k * THREADS], r);
        }
    } else {
        // Guard path (unused for this shape)
        #pragma unroll
        for (int k = 0; k < VEC_PER_THREAD; k++) {
            int i = base + k * THREADS;
            if (i < n_vec4) {
                int4 v = __ldcs(&idx4[i]);
                float4 r;
                r.x = s_vals[v.x];
                r.y = s_vals[v.y];
                r.z = s_vals[v.z];
                r.w = s_vals[v.w];
                __stcs(&out4[i], r);
            }
        }
    }
}

__global__ void gather_tail_kernel(
    const int* __restrict__ idx,
    const float* __restrict__ values,
    float* __restrict__ out,
    int start,
    int n_total)
{
    int i = start + blockIdx.x * blockDim.x + threadIdx.x;
    if (i < n_total) {
        out[i] = values[idx[i]];
    }
}

extern "C" void kernel_launch(void* const* d_in, const int* in_sizes, int n_in,
                              void* d_out, int out_size)
{
    const int* index = (const int*)d_in[0];
    const float* values = (const float*)d_in[1];
    float* out = (float*)d_out;

    int n_total = in_sizes[0];          // 33,554,432
    int n_values = in_sizes[1];         // 100
    int n_vec4 = n_total / 4;           // 8,388,608

    int blocks = (n_vec4 + VEC_PER_BLOCK - 1) / VEC_PER_BLOCK;   // 16384
    gather_final128_kernel<<<blocks, THREADS>>>(
        (const int4*)index, values, (float4*)out, n_vec4, n_values);

    // Tail is 0 for this shape (n_total % 4 == 0); launch only if needed.
    int tail_start = n_vec4 * 4;
    int tail = n_total - tail_start;
    if (tail > 0) {
        int tb = (tail + 255) / 256;
        gather_tail_kernel<<<tb, 256>>>(index, values, out, tail_start, n_total);
    }
}

// round 16
// speedup vs baseline: 1.0323x; 1.0323x over previous
#include <cuda_runtime.h>
#include <cuda_bf16.h>
#include <cstdint>

// out[s,a] = values[index[s,a]]
// index: int32 [33,554,432], values: float [100], out: float [33,554,432]
//
// Probe: sm_103a 256-bit global memory ops (ld/st.global.v8.b32).
// Same bytes/thread as the converged best (64B in / 64B out) but half the
// memory instructions -> half the L1tex wavefront-queue slots per CTA.
// Shape otherwise identical to the best config: 128t, 16384 CTAs,
// smem table, evict-first (.cs) on both touch-once streams.
//
// Sweep (kernel us): MLP=1 41.4 | 256t 37.1 | MLP=8 37.5 | 512t 38.0 |
// persistent 38.2 | repl-table 39.1 | 64t 36.22 | 128t 4xv4 36.19-36.93 (best)
// | stwb 36.99 | no-smem 37.38.

static constexpr int VOCAB_MAX       = 128;
static constexpr int THREADS         = 128;
static constexpr int V8_PER_THREAD   = 2;                        // 2 x 8 ints = 16 elems/thread
static constexpr int V8_PER_BLOCK    = THREADS * V8_PER_THREAD;  // 256 vec8/block

__device__ __forceinline__ void ldg_cs_v8(const int* p, int* r) {
    asm volatile(
        "ld.global.cs.v8.b32 {%0,%1,%2,%3,%4,%5,%6,%7}, [%8];"
        : "=r"(r[0]), "=r"(r[1]), "=r"(r[2]), "=r"(r[3]),
          "=r"(r[4]), "=r"(r[5]), "=r"(r[6]), "=r"(r[7])
        : "l"(p));
}

__device__ __forceinline__ void stg_cs_v8(float* p, const float* r) {
    asm volatile(
        "st.global.cs.v8.b32 [%0], {%1,%2,%3,%4,%5,%6,%7,%8};"
        :: "l"(p),
           "f"(r[0]), "f"(r[1]), "f"(r[2]), "f"(r[3]),
           "f"(r[4]), "f"(r[5]), "f"(r[6]), "f"(r[7])
        : "memory");
}

__global__ void __launch_bounds__(THREADS) gather_v8_kernel(
    const int* __restrict__ index,
    const float* __restrict__ values,
    float* __restrict__ out,
    int n_vec8,
    int n_values)
{
    __shared__ float s_vals[VOCAB_MAX];
    if (threadIdx.x < n_values) {
        s_vals[threadIdx.x] = values[threadIdx.x];
    }
    __syncthreads();

    int base = blockIdx.x * V8_PER_BLOCK + threadIdx.x;   // in vec8 units

    if (base + (V8_PER_THREAD - 1) * THREADS < n_vec8) {
        // Fast path: every block for this shape (4,194,304 / 256 = 16384).
        int v[V8_PER_THREAD][8];
        #pragma unroll
        for (int k = 0; k < V8_PER_THREAD; k++) {
            ldg_cs_v8(index + (size_t)(base + k * THREADS) * 8, v[k]);
        }
        #pragma unroll
        for (int k = 0; k < V8_PER_THREAD; k++) {
            float r[8];
            #pragma unroll
            for (int j = 0; j < 8; j++) {
                r[j] = s_vals[v[k][j]];
            }
            stg_cs_v8(out + (size_t)(base + k * THREADS) * 8, r);
        }
    } else {
        // Guard path (unused for this shape)
        #pragma unroll
        for (int k = 0; k < V8_PER_THREAD; k++) {
            int i = base + k * THREADS;
            if (i < n_vec8) {
                int v[8];
                ldg_cs_v8(index + (size_t)i * 8, v);
                float r[8];
                #pragma unroll
                for (int j = 0; j < 8; j++) {
                    r[j] = s_vals[v[j]];
                }
                stg_cs_v8(out + (size_t)i * 8, r);
            }
        }
    }
}

__global__ void gather_tail_kernel(
    const int* __restrict__ idx,
    const float* __restrict__ values,
    float* __restrict__ out,
    int start,
    int n_total)
{
    int i = start + blockIdx.x * blockDim.x + threadIdx.x;
    if (i < n_total) {
        out[i] = values[idx[i]];
    }
}

extern "C" void kernel_launch(void* const* d_in, const int* in_sizes, int n_in,
                              void* d_out, int out_size)
{
    const int* index = (const int*)d_in[0];
    const float* values = (const float*)d_in[1];
    float* out = (float*)d_out;

    int n_total = in_sizes[0];          // 33,554,432
    int n_values = in_sizes[1];         // 100
    int n_vec8 = n_total / 8;           // 4,194,304

    int blocks = (n_vec8 + V8_PER_BLOCK - 1) / V8_PER_BLOCK;     // 16384
    gather_v8_kernel<<<blocks, THREADS>>>(
        index, values, out, n_vec8, n_values);

    // Tail is 0 for this shape (n_total % 8 == 0); launch only if needed.
    int tail_start = n_vec8 * 8;
    int tail = n_total - tail_start;
    if (tail > 0) {
        int tb = (tail + 255) / 256;
        gather_tail_kernel<<<tb, 256>>>(index, values, out, tail_start, n_total);
    }
}

// round 17
// speedup vs baseline: 1.0338x; 1.0015x over previous
#include <cuda_runtime.h>
#include <cuda_bf16.h>
#include <cstdint>

// out[s,a] = values[index[s,a]]
// index: int32 [33,554,432], values: float [100], out: float [33,554,432]
//
// Final cell of the config cross-product: 256-bit (v8) global ops x 64-thread
// CTAs. Both individually tied-best (36.22us); this combines the smoothest
// per-CTA L1tex burst with the cheapest instruction encoding.
//
// Sweep (kernel us): MLP=1 41.4 | 256t 37.1 | MLP=8 37.5 | 512t 38.0 |
// persistent 38.2 | repl-table 39.1 | no-smem 37.38 | stwb 36.99 |
// 64t v4 36.22 | 128t v4 36.19-36.93 | 128t v8 36.22 (26 regs).
// All best configs statistically tied at the ~36.2us DRAM turnaround floor
// (268MB touch-once -> ~7.4TB/s goodput, 92% of spec).

static constexpr int VOCAB_MAX       = 128;
static constexpr int THREADS         = 64;
static constexpr int V8_PER_THREAD   = 2;                        // 2 x 8 ints = 16 elems/thread
static constexpr int V8_PER_BLOCK    = THREADS * V8_PER_THREAD;  // 128 vec8/block

__device__ __forceinline__ void ldg_cs_v8(const int* p, int* r) {
    asm volatile(
        "ld.global.cs.v8.b32 {%0,%1,%2,%3,%4,%5,%6,%7}, [%8];"
        : "=r"(r[0]), "=r"(r[1]), "=r"(r[2]), "=r"(r[3]),
          "=r"(r[4]), "=r"(r[5]), "=r"(r[6]), "=r"(r[7])
        : "l"(p));
}

__device__ __forceinline__ void stg_cs_v8(float* p, const float* r) {
    asm volatile(
        "st.global.cs.v8.b32 [%0], {%1,%2,%3,%4,%5,%6,%7,%8};"
        :: "l"(p),
           "f"(r[0]), "f"(r[1]), "f"(r[2]), "f"(r[3]),
           "f"(r[4]), "f"(r[5]), "f"(r[6]), "f"(r[7])
        : "memory");
}

__global__ void __launch_bounds__(THREADS) gather_v8_64t_kernel(
    const int* __restrict__ index,
    const float* __restrict__ values,
    float* __restrict__ out,
    int n_vec8,
    int n_values)
{
    __shared__ float s_vals[VOCAB_MAX];
    #pragma unroll
    for (int i = threadIdx.x; i < VOCAB_MAX; i += THREADS) {
        s_vals[i] = (i < n_values) ? values[i] : 0.0f;
    }
    __syncthreads();

    int base = blockIdx.x * V8_PER_BLOCK + threadIdx.x;   // in vec8 units

    if (base + (V8_PER_THREAD - 1) * THREADS < n_vec8) {
        // Fast path: every block for this shape (4,194,304 / 128 = 32768).
        int v[V8_PER_THREAD][8];
        #pragma unroll
        for (int k = 0; k < V8_PER_THREAD; k++) {
            ldg_cs_v8(index + (size_t)(base + k * THREADS) * 8, v[k]);
        }
        #pragma unroll
        for (int k = 0; k < V8_PER_THREAD; k++) {
            float r[8];
            #pragma unroll
            for (int j = 0; j < 8; j++) {
                r[j] = s_vals[v[k][j]];
            }
            stg_cs_v8(out + (size_t)(base + k * THREADS) * 8, r);
        }
    } else {
        // Guard path (unused for this shape)
        #pragma unroll
        for (int k = 0; k < V8_PER_THREAD; k++) {
            int i = base + k * THREADS;
            if (i < n_vec8) {
                int v[8];
                ldg_cs_v8(index + (size_t)i * 8, v);
                float r[8];
                #pragma unroll
                for (int j = 0; j < 8; j++) {
                    r[j] = s_vals[v[j]];
                }
                stg_cs_v8(out + (size_t)i * 8, r);
            }
        }
    }
}

__global__ void gather_tail_kernel(
    const int* __restrict__ idx,
    const float* __restrict__ values,
    float* __restrict__ out,
    int start,
    int n_total)
{
    int i = start + blockIdx.x * blockDim.x + threadIdx.x;
    if (i < n_total) {
        out[i] = values[idx[i]];
    }
}

extern "C" void kernel_launch(void* const* d_in, const int* in_sizes, int n_in,
                              void* d_out, int out_size)
{
    const int* index = (const int*)d_in[0];
    const float* values = (const float*)d_in[1];
    float* out = (float*)d_out;

    int n_total = in_sizes[0];          // 33,554,432
    int n_values = in_sizes[1];         // 100
    int n_vec8 = n_total / 8;           // 4,194,304

    int blocks = (n_vec8 + V8_PER_BLOCK - 1) / V8_PER_BLOCK;     // 32768
    gather_v8_64t_kernel<<<blocks, THREADS>>>(
        index, values, out, n_vec8, n_values);

    // Tail is 0 for this shape (n_total % 8 == 0); launch only if needed.
    int tail_start = n_vec8 * 8;
    int tail = n_total - tail_start;
    if (tail > 0) {
        int tb = (tail + 255) / 256;
        gather_tail_kernel<<<tb, 256>>>(index, values, out, tail_start, n_total);
    }
}